// round 1
// baseline (speedup 1.0000x reference)
#include <cuda_runtime.h>
#include <cstdint>

#define HIDDEN 1024
#define NHEADS 16
#define HDIM   64
#define SEQ    1024
#define BATCH  8
#define NTOK   (BATCH * SEQ)      // 8192
#define QKVW   (3 * HIDDEN)       // 3072

// ---------------------------------------------------------------------------
// Scratch (static device globals -- no allocations allowed)
// ---------------------------------------------------------------------------
__device__ float g_qkv[(size_t)NTOK * QKVW];    // [8192, 3072]
__device__ float g_attn[(size_t)NTOK * HIDDEN]; // [8192, 1024]

// ---------------------------------------------------------------------------
// Packed f32x2 helpers (FFMA2 path: ptxas never auto-fuses; PTX-only)
// ---------------------------------------------------------------------------
__device__ __forceinline__ unsigned long long pack2(float x, float y) {
    unsigned long long r;
    unsigned lo = __float_as_uint(x), hi = __float_as_uint(y);
    asm("mov.b64 %0, {%1, %2};" : "=l"(r) : "r"(lo), "r"(hi));
    return r;
}
__device__ __forceinline__ float2 unpack2(unsigned long long v) {
    unsigned lo, hi;
    asm("mov.b64 {%0, %1}, %2;" : "=r"(lo), "=r"(hi) : "l"(v));
    return make_float2(__uint_as_float(lo), __uint_as_float(hi));
}
__device__ __forceinline__ void fma2(unsigned long long& d,
                                     unsigned long long a,
                                     unsigned long long b) {
    asm("fma.rn.f32x2 %0, %1, %2, %0;" : "+l"(d) : "l"(a), "l"(b));
}
__device__ __forceinline__ void mul2(unsigned long long& d, unsigned long long a) {
    asm("mul.rn.f32x2 %0, %0, %1;" : "+l"(d) : "l"(a));
}

// ---------------------------------------------------------------------------
// GEMM + bias:  C[M,N] = A[M,K] @ B[K,N] + bias[N]
// 128x128 block tile, BK=16, 256 threads, 8 rows x 8 cols per thread
// (cols as two groups of 4: tc..tc+3 and tc+64..tc+67, held as f32x2 pairs)
// ---------------------------------------------------------------------------
#define GBM 128
#define GBN 128
#define GBK 16

__global__ __launch_bounds__(256) void gemm_bias_kernel(
    const float* __restrict__ A, const float* __restrict__ B,
    const float* __restrict__ bias, float* __restrict__ C,
    int M, int N, int K)
{
    __shared__ float As[GBK][GBM + 4];   // stored transposed: As[k][m]
    __shared__ float Bs[GBK][GBN + 4];   // Bs[k][n]

    const int tid = threadIdx.x;
    const int rowBase = blockIdx.y * GBM;
    const int colBase = blockIdx.x * GBN;
    const int tr = (tid >> 4) * 8;       // 0..120: rows tr..tr+7
    const int tc = (tid & 15) * 4;       // 0..60 : cols tc..tc+3 and +64

    unsigned long long acc[8][4];
    #pragma unroll
    for (int i = 0; i < 8; i++)
        #pragma unroll
        for (int j = 0; j < 4; j++) acc[i][j] = 0ull;

    const float* Ab = A + rowBase * K;
    const float* Bb = B + colBase;

    for (int kb = 0; kb < K; kb += GBK) {
        #pragma unroll
        for (int i = 0; i < 2; i++) {
            int e = tid + i * 256;
            // A tile: 128x16 = 512 float4
            int ar = e >> 2;
            int ac = (e & 3) << 2;
            float4 va = *(const float4*)(Ab + ar * K + kb + ac);
            As[ac + 0][ar] = va.x; As[ac + 1][ar] = va.y;
            As[ac + 2][ar] = va.z; As[ac + 3][ar] = va.w;
            // B tile: 16x128 = 512 float4
            int br = e >> 5;
            int bc = (e & 31) << 2;
            *(float4*)&Bs[br][bc] = *(const float4*)(Bb + (kb + br) * N + bc);
        }
        __syncthreads();

        #pragma unroll
        for (int k = 0; k < GBK; k++) {
            float a[8];
            *(float4*)&a[0] = *(const float4*)&As[k][tr];
            *(float4*)&a[4] = *(const float4*)&As[k][tr + 4];
            const unsigned long long* bp0 =
                (const unsigned long long*)&Bs[k][tc];
            const unsigned long long* bp1 =
                (const unsigned long long*)&Bs[k][tc + 64];
            unsigned long long b0 = bp0[0], b1 = bp0[1];
            unsigned long long b2 = bp1[0], b3 = bp1[1];
            #pragma unroll
            for (int i = 0; i < 8; i++) {
                unsigned long long a2 = pack2(a[i], a[i]);
                fma2(acc[i][0], a2, b0);
                fma2(acc[i][1], a2, b1);
                fma2(acc[i][2], a2, b2);
                fma2(acc[i][3], a2, b3);
            }
        }
        __syncthreads();
    }

    float bs0[4], bs1[4];
    #pragma unroll
    for (int j = 0; j < 4; j++) {
        bs0[j] = bias[colBase + tc + j];
        bs1[j] = bias[colBase + tc + 64 + j];
    }
    #pragma unroll
    for (int i = 0; i < 8; i++) {
        float* cp = C + (rowBase + tr + i) * N + colBase;
        float2 p0 = unpack2(acc[i][0]), p1 = unpack2(acc[i][1]);
        float2 p2 = unpack2(acc[i][2]), p3 = unpack2(acc[i][3]);
        float4 v0 = make_float4(p0.x + bs0[0], p0.y + bs0[1],
                                p1.x + bs0[2], p1.y + bs0[3]);
        float4 v1 = make_float4(p2.x + bs1[0], p2.y + bs1[1],
                                p3.x + bs1[2], p3.y + bs1[3]);
        *(float4*)(cp + tc)      = v0;
        *(float4*)(cp + tc + 64) = v1;
    }
}

// ---------------------------------------------------------------------------
// Flash attention (fp32, online softmax). One block = 64 q rows of one (b,h).
// qkv layout: [token, 3072]; Q at col h*64, K at 1024+h*64, V at 2048+h*64.
// out: [token, 1024] at col h*64  (i.e. [B,S,H,D] flattened token-major)
// Thread layout: r = tid/4 (row), col pairs c0+8j with c0 = 2*(tid&3).
// ---------------------------------------------------------------------------
#define FBM 64
#define FBN 64
#define KQS 66   // padded stride for Q and K/P tiles
#define FLASH_SMEM ((64 * KQS + 64 * KQS + 64 * 64) * 4)

__global__ __launch_bounds__(256) void flash_attn_kernel(
    const float* __restrict__ qkv, float* __restrict__ out)
{
    extern __shared__ float sm[];
    float* sQ = sm;                  // [64][66]  Q row-major (scaled)
    float* sK = sm + 64 * KQS;       // [64][66]  K d-major; reused as P[r][key]
    float* sV = sm + 2 * 64 * KQS;   // [64][64]  V row-major

    const int tid = threadIdx.x;
    const int b = blockIdx.z, h = blockIdx.y;
    const int q0 = blockIdx.x * FBM;

    const float* base = qkv + (b * SEQ) * QKVW + h * HDIM;

    // Load Q tile (scaled by 1/sqrt(64))
    #pragma unroll
    for (int i = 0; i < 4; i++) {
        int e = tid + i * 256;
        int r = e >> 4, c = (e & 15) << 2;
        float4 v = *(const float4*)(base + (q0 + r) * QKVW + c);
        float* q = &sQ[r * KQS + c];
        q[0] = v.x * 0.125f; q[1] = v.y * 0.125f;
        q[2] = v.z * 0.125f; q[3] = v.w * 0.125f;
    }

    const int r  = tid >> 2;
    const int c0 = (tid & 3) * 2;

    float m = -1e30f, l = 0.f;
    unsigned long long o2[8];
    #pragma unroll
    for (int j = 0; j < 8; j++) o2[j] = 0ull;

    for (int kb = 0; kb < SEQ; kb += FBN) {
        __syncthreads();   // prev iter's P/V reads done before overwrite
        #pragma unroll
        for (int i = 0; i < 4; i++) {
            int e = tid + i * 256;
            int kr = e >> 4, kc = (e & 15) << 2;
            float4 v = *(const float4*)(base + HIDDEN + (kb + kr) * QKVW + kc);
            sK[(kc + 0) * KQS + kr] = v.x;
            sK[(kc + 1) * KQS + kr] = v.y;
            sK[(kc + 2) * KQS + kr] = v.z;
            sK[(kc + 3) * KQS + kr] = v.w;
            float4 w = *(const float4*)(base + 2 * HIDDEN + (kb + kr) * QKVW + kc);
            *(float4*)&sV[kr * 64 + kc] = w;
        }
        __syncthreads();

        // S = Q K^T  (thread's 16 cols as 8 f32x2 pairs at c0 + 8j)
        unsigned long long s2[8];
        #pragma unroll
        for (int j = 0; j < 8; j++) s2[j] = 0ull;
        #pragma unroll 8
        for (int k = 0; k < 64; k++) {
            float q = sQ[r * KQS + k];
            unsigned long long q2 = pack2(q, q);
            const unsigned long long* kp =
                (const unsigned long long*)&sK[k * KQS + c0];
            #pragma unroll
            for (int j = 0; j < 8; j++)
                fma2(s2[j], q2, kp[4 * j]);
        }

        float sv[16];
        #pragma unroll
        for (int j = 0; j < 8; j++) {
            float2 t = unpack2(s2[j]);
            sv[2 * j] = t.x; sv[2 * j + 1] = t.y;
        }
        float tm = sv[0];
        #pragma unroll
        for (int t = 1; t < 16; t++) tm = fmaxf(tm, sv[t]);
        tm = fmaxf(tm, __shfl_xor_sync(0xffffffffu, tm, 1));
        tm = fmaxf(tm, __shfl_xor_sync(0xffffffffu, tm, 2));
        float mn = fmaxf(m, tm);
        float corr = __expf(m - mn);
        m = mn;
        float ls = 0.f;
        #pragma unroll
        for (int t = 0; t < 16; t++) {
            sv[t] = __expf(sv[t] - mn);
            ls += sv[t];
        }
        ls += __shfl_xor_sync(0xffffffffu, ls, 1);
        ls += __shfl_xor_sync(0xffffffffu, ls, 2);
        l = l * corr + ls;
        unsigned long long cc = pack2(corr, corr);
        #pragma unroll
        for (int j = 0; j < 8; j++) mul2(o2[j], cc);

        __syncthreads();   // all S reads of sK done -> safe to write P there
        #pragma unroll
        for (int j = 0; j < 8; j++)
            *(float2*)&sK[r * KQS + c0 + 8 * j] =
                make_float2(sv[2 * j], sv[2 * j + 1]);
        __syncthreads();

        // O += P @ V
        #pragma unroll 8
        for (int k = 0; k < 64; k++) {
            float p = sK[r * KQS + k];
            unsigned long long p2 = pack2(p, p);
            const unsigned long long* vp =
                (const unsigned long long*)&sV[k * 64 + c0];
            #pragma unroll
            for (int j = 0; j < 8; j++)
                fma2(o2[j], p2, vp[4 * j]);
        }
    }

    float inv = 1.0f / l;
    float* orow = out + (b * SEQ + q0 + r) * HIDDEN + h * HDIM + c0;
    #pragma unroll
    for (int j = 0; j < 8; j++) {
        float2 t = unpack2(o2[j]);
        *(float2*)(orow + 8 * j) = make_float2(t.x * inv, t.y * inv);
    }
}

// ---------------------------------------------------------------------------
// Launch
// ---------------------------------------------------------------------------
extern "C" void kernel_launch(void* const* d_in, const int* in_sizes, int n_in,
                              void* d_out, int out_size)
{
    const float* query = (const float*)d_in[0];
    const float* w_qkv = (const float*)d_in[1];
    const float* b_qkv = (const float*)d_in[2];
    const float* w_o   = (const float*)d_in[3];
    const float* b_o   = (const float*)d_in[4];
    float* out = (float*)d_out;

    void* pqkv  = nullptr;
    void* pattn = nullptr;
    cudaGetSymbolAddress(&pqkv,  g_qkv);
    cudaGetSymbolAddress(&pattn, g_attn);
    float* qkv  = (float*)pqkv;
    float* attn = (float*)pattn;

    cudaFuncSetAttribute(flash_attn_kernel,
                         cudaFuncAttributeMaxDynamicSharedMemorySize,
                         FLASH_SMEM);

    // 1) QKV = X @ W_qkv + b_qkv      [8192,1024]x[1024,3072]
    dim3 g1(QKVW / GBN, NTOK / GBM);
    gemm_bias_kernel<<<g1, 256>>>(query, w_qkv, b_qkv, qkv,
                                  NTOK, QKVW, HIDDEN);

    // 2) attention -> attn [8192,1024] (token-major, head-contig cols)
    dim3 g2(SEQ / FBM, NHEADS, BATCH);
    flash_attn_kernel<<<g2, 256, FLASH_SMEM>>>(qkv, attn);

    // 3) out = attn @ W_o + b_o       [8192,1024]x[1024,1024]
    dim3 g3(HIDDEN / GBN, NTOK / GBM);
    gemm_bias_kernel<<<g3, 256>>>(attn, w_o, b_o, out,
                                  NTOK, HIDDEN, HIDDEN);
}

// round 12
// speedup vs baseline: 2.1457x; 2.1457x over previous
#include <cuda_runtime.h>
#include <cuda_fp16.h>
#include <cstdint>

#define HIDDEN 1024
#define NHEADS 16
#define HDIM   64
#define SEQ    1024
#define BATCH  8
#define NTOK   (BATCH * SEQ)      // 8192
#define QKVW   (3 * HIDDEN)       // 3072

typedef unsigned long long u64;

// ---------------------------------------------------------------------------
// Static device scratch (no allocations allowed)
// ---------------------------------------------------------------------------
__device__ float g_qkv[(size_t)NTOK * QKVW];        // fp32 QKV [8192,3072]
__device__ __half g_xhi[(size_t)NTOK * HIDDEN];     // X hi/lo fp16
__device__ __half g_xlo[(size_t)NTOK * HIDDEN];
__device__ __half g_ahi[(size_t)NTOK * HIDDEN];     // attn out hi/lo fp16
__device__ __half g_alo[(size_t)NTOK * HIDDEN];
__device__ __half g_wq[(size_t)QKVW * HIDDEN];      // W_qkv^T fp16 [3072,1024]
__device__ __half g_wo[(size_t)HIDDEN * HIDDEN];    // W_o^T  fp16 [1024,1024]

// ---------------------------------------------------------------------------
// Helpers (all plain sm_103-legal: no 'a'-suffix features)
// ---------------------------------------------------------------------------
__device__ __forceinline__ uint32_t smem_u32(const void* p) {
    uint32_t a;
    asm("{ .reg .u64 t; cvta.to.shared.u64 t, %1; cvt.u32.u64 %0, t; }"
        : "=r"(a) : "l"(p));
    return a;
}
__device__ __forceinline__ u64 pack2(float x, float y) {
    u64 r; unsigned lo = __float_as_uint(x), hi = __float_as_uint(y);
    asm("mov.b64 %0, {%1, %2};" : "=l"(r) : "r"(lo), "r"(hi));
    return r;
}
__device__ __forceinline__ float2 unpack2(u64 v) {
    unsigned lo, hi;
    asm("mov.b64 {%0, %1}, %2;" : "=r"(lo), "=r"(hi) : "l"(v));
    return make_float2(__uint_as_float(lo), __uint_as_float(hi));
}
__device__ __forceinline__ void fma2(u64& d, u64 a, u64 b) {
    asm("fma.rn.f32x2 %0, %1, %2, %0;" : "+l"(d) : "l"(a), "l"(b));
}
__device__ __forceinline__ void mul2(u64& d, u64 a) {
    asm("mul.rn.f32x2 %0, %0, %1;" : "+l"(d) : "l"(a));
}
__device__ __forceinline__ void split1h(float x, __half& h, __half& l) {
    h = __float2half_rn(x);
    l = __float2half_rn(x - __half2float(h));
}
__device__ __forceinline__ void cp16(uint32_t dst, const void* src) {
    asm volatile("cp.async.cg.shared.global [%0], [%1], 16;"
                 :: "r"(dst), "l"(src) : "memory");
}
#define CP_COMMIT() asm volatile("cp.async.commit_group;" ::: "memory")
#define CP_WAIT(n)  asm volatile("cp.async.wait_group %0;" :: "n"(n) : "memory")

#define LDSM4(r, addr)                                                         \
    asm volatile("ldmatrix.sync.aligned.m8n8.x4.shared.b16 {%0,%1,%2,%3}, [%4];" \
        : "=r"((r)[0]), "=r"((r)[1]), "=r"((r)[2]), "=r"((r)[3]) : "r"(addr))

#define MMA16816(c, a, b0, b1)                                                 \
    asm volatile("mma.sync.aligned.m16n8k16.row.col.f32.f16.f16.f32 "          \
        "{%0,%1,%2,%3}, {%4,%5,%6,%7}, {%8,%9}, {%0,%1,%2,%3};"                \
        : "+f"((c)[0]), "+f"((c)[1]), "+f"((c)[2]), "+f"((c)[3])               \
        : "r"((a)[0]), "r"((a)[1]), "r"((a)[2]), "r"((a)[3]), "r"(b0), "r"(b1))

// ---------------------------------------------------------------------------
// Conversion kernels
// ---------------------------------------------------------------------------
__global__ void split_fp16_kernel(const float4* __restrict__ in,
                                  __half2* __restrict__ hi,
                                  __half2* __restrict__ lo, int n4)
{
    int i = blockIdx.x * blockDim.x + threadIdx.x;
    if (i >= n4) return;
    float4 v = in[i];
    __half h0, h1, h2, h3, l0, l1, l2, l3;
    split1h(v.x, h0, l0); split1h(v.y, h1, l1);
    split1h(v.z, h2, l2); split1h(v.w, h3, l3);
    hi[2 * i]     = __halves2half2(h0, h1);
    hi[2 * i + 1] = __halves2half2(h2, h3);
    lo[2 * i]     = __halves2half2(l0, l1);
    lo[2 * i + 1] = __halves2half2(l2, l3);
}

// W [K,N] row-major -> T[n][k] = W[k][n], single fp16
__global__ void transpose_fp16_kernel(const float* __restrict__ W,
                                      __half* __restrict__ T, int K, int N)
{
    __shared__ float t[32][33];
    int n0 = blockIdx.x * 32, k0 = blockIdx.y * 32;
    int tx = threadIdx.x, ty = threadIdx.y;
    #pragma unroll
    for (int i = 0; i < 4; i++)
        t[ty + 8 * i][tx] = W[(size_t)(k0 + ty + 8 * i) * N + n0 + tx];
    __syncthreads();
    #pragma unroll
    for (int i = 0; i < 4; i++)
        T[(size_t)(n0 + ty + 8 * i) * K + k0 + tx] =
            __float2half_rn(t[tx][ty + 8 * i]);
}

// ---------------------------------------------------------------------------
// HMMA GEMM:  C[M,N] = (Ah+Al) @ B^T + bias   (A split fp16, B single fp16)
// 128x128 CTA tile, 8 warps (4m x 2n), warp tile 32x64, K-chunks of 32,
// cp.async double buffer, ldmatrix fragments, mma.sync m16n8k16 f16->f32.
// ---------------------------------------------------------------------------
#define BM 128
#define BN 128
#define BK 32
#define PAD 40                     // half units per row (80 B; conflict-free)
#define MATSZ (128 * PAD)          // 5120 halves per matrix tile
#define BUFSZ (3 * MATSZ)          // Ah, Al, B
#define GEMM_SMEM (512 + 2 * BUFSZ * 2)   // bias + 2 buffers (bytes) = 61952

__global__ __launch_bounds__(256) void gemm_mma_kernel(
    const __half* __restrict__ Ah, const __half* __restrict__ Al,
    const __half* __restrict__ B,  const float* __restrict__ bias,
    float* __restrict__ C, int N, int K)
{
    extern __shared__ __align__(16) char smem[];
    float* sBias = (float*)smem;
    __half* sBuf = (__half*)(smem + 512);
    const uint32_t sbase = smem_u32(sBuf);

    const int tid = threadIdx.x;
    const int lane = tid & 31;
    const int wid = tid >> 5;
    const int wm = wid & 3;              // 0..3
    const int wn = wid >> 2;             // 0..1
    const int rowBase = blockIdx.y * BM;
    const int colBase = blockIdx.x * BN;
    const int warpRow = wm * 32;
    const int warpCol = wn * 64;
    const int NCH = K / BK;

    if (tid < 128) sBias[tid] = bias[colBase + tid];

    float acc[2][8][4];
    #pragma unroll
    for (int a = 0; a < 2; a++)
        #pragma unroll
        for (int n = 0; n < 8; n++)
            #pragma unroll
            for (int q = 0; q < 4; q++) acc[a][n][q] = 0.f;

    // ldmatrix lane addressing (constant across chunks)
    const int tile = lane >> 3, trow = lane & 7;
    const int aRow = (tile & 1) * 8 + trow;   // + warpRow + am*16
    const int aK   = (tile >> 1) * 8;         // + ks*16
    const int bRow = (tile >> 1) * 8 + trow;  // + warpCol + np*16
    const int bK   = (tile & 1) * 8;          // + ks*16

    // prologue: load chunk 0 into buffer 0
    {
        #pragma unroll
        for (int it = 0; it < 2; it++) {
            int idx = tid + it * 256;
            int row = idx >> 2, seg = idx & 3;
            uint32_t d = sbase + (uint32_t)(row * PAD + seg * 8) * 2;
            size_t ga = (size_t)(rowBase + row) * K + seg * 8;
            size_t gb = (size_t)(colBase + row) * K + seg * 8;
            cp16(d,              Ah + ga);
            cp16(d + MATSZ * 2,  Al + ga);
            cp16(d + MATSZ * 4,  B + gb);
        }
        CP_COMMIT();
    }

    for (int c = 0; c < NCH; c++) {
        if (c + 1 < NCH) {
            int k0 = (c + 1) * BK;
            uint32_t bb = sbase + (uint32_t)((c + 1) & 1) * (BUFSZ * 2);
            #pragma unroll
            for (int it = 0; it < 2; it++) {
                int idx = tid + it * 256;
                int row = idx >> 2, seg = idx & 3;
                uint32_t d = bb + (uint32_t)(row * PAD + seg * 8) * 2;
                size_t ga = (size_t)(rowBase + row) * K + k0 + seg * 8;
                size_t gb = (size_t)(colBase + row) * K + k0 + seg * 8;
                cp16(d,              Ah + ga);
                cp16(d + MATSZ * 2,  Al + ga);
                cp16(d + MATSZ * 4,  B + gb);
            }
            CP_COMMIT();
            CP_WAIT(1);
        } else {
            CP_WAIT(0);
        }
        __syncthreads();

        uint32_t bb = sbase + (uint32_t)(c & 1) * (BUFSZ * 2);
        uint32_t aAh = bb, aAl = bb + MATSZ * 2, aB = bb + MATSZ * 4;

        #pragma unroll
        for (int ks = 0; ks < 2; ks++) {
            uint32_t afh[2][4], afl[2][4];
            #pragma unroll
            for (int am = 0; am < 2; am++) {
                uint32_t off =
                    (uint32_t)((warpRow + am * 16 + aRow) * PAD + ks * 16 + aK) * 2;
                LDSM4(afh[am], aAh + off);
                LDSM4(afl[am], aAl + off);
            }
            #pragma unroll
            for (int np = 0; np < 4; np++) {
                uint32_t bf[4];
                uint32_t off =
                    (uint32_t)((warpCol + np * 16 + bRow) * PAD + ks * 16 + bK) * 2;
                LDSM4(bf, aB + off);
                #pragma unroll
                for (int h = 0; h < 2; h++) {
                    int na = np * 2 + h;
                    uint32_t b0 = bf[h * 2], b1 = bf[h * 2 + 1];
                    #pragma unroll
                    for (int am = 0; am < 2; am++) {
                        MMA16816(acc[am][na], afl[am], b0, b1);
                        MMA16816(acc[am][na], afh[am], b0, b1);
                    }
                }
            }
        }
        __syncthreads();
    }

    // epilogue: add bias, write fp32
    const int qr = lane >> 2;
    const int qc = (lane & 3) * 2;
    #pragma unroll
    for (int am = 0; am < 2; am++) {
        #pragma unroll
        for (int na = 0; na < 8; na++) {
            int col = warpCol + na * 8 + qc;
            float b0 = sBias[col], b1 = sBias[col + 1];
            int r0 = rowBase + warpRow + am * 16 + qr;
            float* p0 = C + (size_t)r0 * N + colBase + col;
            float* p1 = C + (size_t)(r0 + 8) * N + colBase + col;
            *(float2*)p0 = make_float2(acc[am][na][0] + b0, acc[am][na][1] + b1);
            *(float2*)p1 = make_float2(acc[am][na][2] + b0, acc[am][na][3] + b1);
        }
    }
}

// ---------------------------------------------------------------------------
// Flash attention fp32, 2 q-rows per thread, 128 threads, FBM=64, FBN=64.
// Epilogue writes fp16 hi/lo split directly (feeds proj GEMM A operand).
// ---------------------------------------------------------------------------
#define FBM 64
#define FBN 64
#define KQS 66
#define FLASH_SMEM ((64 * KQS + 64 * KQS + 64 * 64) * 4)

__global__ __launch_bounds__(128) void flash_attn_kernel(
    const float* __restrict__ qkv,
    __half* __restrict__ ohi,
    __half* __restrict__ olo)
{
    extern __shared__ __align__(1024) float sm[];
    float* sQ = sm;                  // [64][66] row-major (scaled)
    float* sK = sm + 64 * KQS;       // [64][66] K d-major; reused as P row-major
    float* sV = sm + 2 * 64 * KQS;   // [64][64] row-major

    const int tid = threadIdx.x;
    const int b = blockIdx.z, h = blockIdx.y;
    const int q0 = blockIdx.x * FBM;
    const float* base = qkv + (size_t)(b * SEQ) * QKVW + h * HDIM;

    #pragma unroll
    for (int i = 0; i < 8; i++) {
        int e = tid + i * 128;
        int r = e >> 4, c = (e & 15) << 2;
        float4 v = *(const float4*)(base + (size_t)(q0 + r) * QKVW + c);
        float* q = &sQ[r * KQS + c];
        q[0] = v.x * 0.125f; q[1] = v.y * 0.125f;
        q[2] = v.z * 0.125f; q[3] = v.w * 0.125f;
    }

    const int rg = tid >> 2;
    const int r0 = rg * 2, r1 = r0 + 1;
    const int c0 = (tid & 3) * 2;

    float m0 = -1e30f, l0 = 0.f, m1 = -1e30f, l1 = 0.f;
    u64 o0[8], o1[8];
    #pragma unroll
    for (int j = 0; j < 8; j++) { o0[j] = 0ull; o1[j] = 0ull; }

    for (int kb = 0; kb < SEQ; kb += FBN) {
        __syncthreads();
        #pragma unroll
        for (int i = 0; i < 8; i++) {
            int e = tid + i * 128;
            int kr = e >> 4, kc = (e & 15) << 2;
            float4 v = *(const float4*)(base + HIDDEN + (size_t)(kb + kr) * QKVW + kc);
            sK[(kc + 0) * KQS + kr] = v.x;
            sK[(kc + 1) * KQS + kr] = v.y;
            sK[(kc + 2) * KQS + kr] = v.z;
            sK[(kc + 3) * KQS + kr] = v.w;
            float4 w = *(const float4*)(base + 2 * HIDDEN + (size_t)(kb + kr) * QKVW + kc);
            *(float4*)&sV[kr * 64 + kc] = w;
        }
        __syncthreads();

        u64 sa[8], sb[8];
        #pragma unroll
        for (int j = 0; j < 8; j++) { sa[j] = 0ull; sb[j] = 0ull; }
        #pragma unroll 4
        for (int k = 0; k < 64; k++) {
            float qa = sQ[r0 * KQS + k];
            float qb = sQ[r1 * KQS + k];
            u64 qa2 = pack2(qa, qa), qb2 = pack2(qb, qb);
            const u64* kp = (const u64*)&sK[k * KQS + c0];
            #pragma unroll
            for (int j = 0; j < 8; j++) {
                u64 kv = kp[4 * j];
                fma2(sa[j], qa2, kv);
                fma2(sb[j], qb2, kv);
            }
        }

        float va[16], vb[16];
        #pragma unroll
        for (int j = 0; j < 8; j++) {
            float2 t = unpack2(sa[j]); va[2 * j] = t.x; va[2 * j + 1] = t.y;
            float2 u = unpack2(sb[j]); vb[2 * j] = u.x; vb[2 * j + 1] = u.y;
        }
        float ta = va[0], tb = vb[0];
        #pragma unroll
        for (int t = 1; t < 16; t++) { ta = fmaxf(ta, va[t]); tb = fmaxf(tb, vb[t]); }
        ta = fmaxf(ta, __shfl_xor_sync(0xffffffffu, ta, 1));
        ta = fmaxf(ta, __shfl_xor_sync(0xffffffffu, ta, 2));
        tb = fmaxf(tb, __shfl_xor_sync(0xffffffffu, tb, 1));
        tb = fmaxf(tb, __shfl_xor_sync(0xffffffffu, tb, 2));
        float mn0 = fmaxf(m0, ta), mn1 = fmaxf(m1, tb);
        float corr0 = __expf(m0 - mn0), corr1 = __expf(m1 - mn1);
        m0 = mn0; m1 = mn1;
        float ls0 = 0.f, ls1 = 0.f;
        #pragma unroll
        for (int t = 0; t < 16; t++) {
            va[t] = __expf(va[t] - mn0); ls0 += va[t];
            vb[t] = __expf(vb[t] - mn1); ls1 += vb[t];
        }
        ls0 += __shfl_xor_sync(0xffffffffu, ls0, 1);
        ls0 += __shfl_xor_sync(0xffffffffu, ls0, 2);
        ls1 += __shfl_xor_sync(0xffffffffu, ls1, 1);
        ls1 += __shfl_xor_sync(0xffffffffu, ls1, 2);
        l0 = l0 * corr0 + ls0;
        l1 = l1 * corr1 + ls1;
        u64 cc0 = pack2(corr0, corr0), cc1 = pack2(corr1, corr1);
        #pragma unroll
        for (int j = 0; j < 8; j++) { mul2(o0[j], cc0); mul2(o1[j], cc1); }

        __syncthreads();
        #pragma unroll
        for (int j = 0; j < 8; j++) {
            *(float2*)&sK[r0 * KQS + c0 + 8 * j] = make_float2(va[2 * j], va[2 * j + 1]);
            *(float2*)&sK[r1 * KQS + c0 + 8 * j] = make_float2(vb[2 * j], vb[2 * j + 1]);
        }
        __syncthreads();

        #pragma unroll 4
        for (int k = 0; k < 64; k++) {
            float pa = sK[r0 * KQS + k];
            float pb = sK[r1 * KQS + k];
            u64 pa2 = pack2(pa, pa), pb2 = pack2(pb, pb);
            const u64* vp = (const u64*)&sV[k * 64 + c0];
            #pragma unroll
            for (int j = 0; j < 8; j++) {
                u64 vv = vp[4 * j];
                fma2(o0[j], pa2, vv);
                fma2(o1[j], pb2, vv);
            }
        }
    }

    // Epilogue: normalize + fp16 hi/lo split, written directly to proj inputs.
    float inv0 = 1.0f / l0, inv1 = 1.0f / l1;
    size_t off0 = (size_t)(b * SEQ + q0 + r0) * HIDDEN + h * HDIM + c0;
    size_t off1 = (size_t)(b * SEQ + q0 + r1) * HIDDEN + h * HDIM + c0;
    #pragma unroll
    for (int j = 0; j < 8; j++) {
        float2 t = unpack2(o0[j]);
        float x0 = t.x * inv0, x1 = t.y * inv0;
        __half h0, h1, lo0, lo1;
        split1h(x0, h0, lo0); split1h(x1, h1, lo1);
        *(__half2*)(ohi + off0 + 8 * j) = __halves2half2(h0, h1);
        *(__half2*)(olo + off0 + 8 * j) = __halves2half2(lo0, lo1);

        float2 u = unpack2(o1[j]);
        float y0 = u.x * inv1, y1 = u.y * inv1;
        split1h(y0, h0, lo0); split1h(y1, h1, lo1);
        *(__half2*)(ohi + off1 + 8 * j) = __halves2half2(h0, h1);
        *(__half2*)(olo + off1 + 8 * j) = __halves2half2(lo0, lo1);
    }
}

// ---------------------------------------------------------------------------
// Launch
// ---------------------------------------------------------------------------
extern "C" void kernel_launch(void* const* d_in, const int* in_sizes, int n_in,
                              void* d_out, int out_size)
{
    const float* query = (const float*)d_in[0];
    const float* w_qkv = (const float*)d_in[1];
    const float* b_qkv = (const float*)d_in[2];
    const float* w_o   = (const float*)d_in[3];
    const float* b_o   = (const float*)d_in[4];
    float* out = (float*)d_out;

    void *pqkv, *pxh, *pxl, *pah, *pal, *pwq, *pwo;
    cudaGetSymbolAddress(&pqkv, g_qkv);
    cudaGetSymbolAddress(&pxh,  g_xhi);
    cudaGetSymbolAddress(&pxl,  g_xlo);
    cudaGetSymbolAddress(&pah,  g_ahi);
    cudaGetSymbolAddress(&pal,  g_alo);
    cudaGetSymbolAddress(&pwq,  g_wq);
    cudaGetSymbolAddress(&pwo,  g_wo);

    cudaFuncSetAttribute(gemm_mma_kernel,
                         cudaFuncAttributeMaxDynamicSharedMemorySize, GEMM_SMEM);
    cudaFuncSetAttribute(flash_attn_kernel,
                         cudaFuncAttributeMaxDynamicSharedMemorySize, FLASH_SMEM);

    // converts: X -> fp16 hi/lo; W_qkv, W_o -> transposed single fp16
    int n4x = NTOK * HIDDEN / 4;
    split_fp16_kernel<<<n4x / 256, 256>>>((const float4*)query,
        (__half2*)pxh, (__half2*)pxl, n4x);
    transpose_fp16_kernel<<<dim3(QKVW / 32, HIDDEN / 32), dim3(32, 8)>>>(
        w_qkv, (__half*)pwq, HIDDEN, QKVW);
    transpose_fp16_kernel<<<dim3(HIDDEN / 32, HIDDEN / 32), dim3(32, 8)>>>(
        w_o, (__half*)pwo, HIDDEN, HIDDEN);

    // 1) QKV = X @ W_qkv + b_qkv
    gemm_mma_kernel<<<dim3(QKVW / BN, NTOK / BM), 256, GEMM_SMEM>>>(
        (const __half*)pxh, (const __half*)pxl, (const __half*)pwq,
        b_qkv, (float*)pqkv, QKVW, HIDDEN);

    // 2) attention -> fp16 hi/lo directly
    flash_attn_kernel<<<dim3(SEQ / FBM, NHEADS, BATCH), 128, FLASH_SMEM>>>(
        (const float*)pqkv, (__half*)pah, (__half*)pal);

    // 3) out = attn @ W_o + b_o
    gemm_mma_kernel<<<dim3(HIDDEN / BN, NTOK / BM), 256, GEMM_SMEM>>>(
        (const __half*)pah, (const __half*)pal, (const __half*)pwo,
        b_o, out, HIDDEN, HIDDEN);
}